// round 12
// baseline (speedup 1.0000x reference)
#include <cuda_runtime.h>
#include <cuda_bf16.h>
#include <cstdint>

// ---------------------------------------------------------------------------
// Problem constants
// ---------------------------------------------------------------------------
#define HID   4096
#define LQ    128
#define CTX   896
#define TT    1024
#define STATE 3072
#define SS    4096
#define HQ    32
#define HKV   8
#define DD    128
#define HALF  64
#define EPS   1e-6f
#define SCALE 0.08838834764831845f

#define OUT_ELEMS   (LQ * HID)
#define K_ELEMS     (HKV * TT * DD)

// ---------------------------------------------------------------------------
// Scratch (device globals)
// ---------------------------------------------------------------------------
__device__ float g_qproj[LQ * HQ * DD];
__device__ float g_kproj[TT * HKV * DD];
__device__ float g_vproj[TT * HKV * DD];
__device__ float g_qh[HQ * LQ * DD];
__device__ float g_scores[HQ * LQ * SS];          // 64 MB
__device__ float g_oacc[LQ * HQ * DD];
__device__ __nv_bfloat16 g_ph[HQ * LQ * SS];      // softmax P hi
__device__ __nv_bfloat16 g_pl[HQ * LQ * SS];      // softmax P lo
__device__ __nv_bfloat16 g_vth[HKV * DD * SS];    // V^T hi  [g][d][s]
__device__ __nv_bfloat16 g_vtl[HKV * DD * SS];    // V^T lo

// ---------------------------------------------------------------------------
// mma.sync m16n8k16 bf16 (sm_80+, legal on plain sm_103 PTX target)
// ---------------------------------------------------------------------------
__device__ __forceinline__ void mma16816(float* d, const uint32_t* a, const uint32_t* b)
{
    asm volatile(
        "mma.sync.aligned.m16n8k16.row.col.f32.bf16.bf16.f32 "
        "{%0,%1,%2,%3}, {%4,%5,%6,%7}, {%8,%9}, {%0,%1,%2,%3};"
        : "+f"(d[0]), "+f"(d[1]), "+f"(d[2]), "+f"(d[3])
        : "r"(a[0]), "r"(a[1]), "r"(a[2]), "r"(a[3]), "r"(b[0]), "r"(b[1]));
}

// ---------------------------------------------------------------------------
// SMEM tile geometry: 128 rows x 64 bf16 cols, rows padded to 144 bytes
// (72 bf16) so fragment LDS is bank-conflict-free (bank = 4*(lane/4)+lane%4).
// ---------------------------------------------------------------------------
#define AROW_B 144
#define TILE_B (128 * AROW_B)          // 18432
#define STAGE_B (4 * TILE_B)           // Ah | Al | Bh | Bl
#define SMEM_BYTES (2 * STAGE_B)       // 147456, double buffered

__device__ __forceinline__ void load_f32_tile(
    const float* __restrict__ pa, const float* __restrict__ pb, long rows1,
    long K, int rowBase, int kk, char* smHi, char* smLo, int tid)
{
    const int r = tid >> 1;
    const int cb = (tid & 1) * 32;
    const long row = rowBase + r;
    const float* rp = (row < rows1) ? (pa + row * K) : (pb + (row - rows1) * K);
    rp += kk + cb;
    char* hB = smHi + r * AROW_B + cb * 2;
    char* lB = smLo + r * AROW_B + cb * 2;
    #pragma unroll
    for (int i = 0; i < 8; i++) {
        float4 v = *(const float4*)(rp + i * 4);
        __nv_bfloat162 h01 = __floats2bfloat162_rn(v.x, v.y);
        __nv_bfloat162 h23 = __floats2bfloat162_rn(v.z, v.w);
        float2 f01 = __bfloat1622float2(h01);
        float2 f23 = __bfloat1622float2(h23);
        __nv_bfloat162 l01 = __floats2bfloat162_rn(v.x - f01.x, v.y - f01.y);
        __nv_bfloat162 l23 = __floats2bfloat162_rn(v.z - f23.x, v.w - f23.y);
        *(uint2*)(hB + i * 8) = make_uint2(*(const uint32_t*)&h01, *(const uint32_t*)&h23);
        *(uint2*)(lB + i * 8) = make_uint2(*(const uint32_t*)&l01, *(const uint32_t*)&l23);
    }
}

__device__ __forceinline__ void load_bf16_tile(
    const __nv_bfloat16* __restrict__ hi, const __nv_bfloat16* __restrict__ lo,
    long K, int rowBase, int kk, char* smHi, char* smLo, int tid)
{
    const int r = tid >> 1;
    const int cb = (tid & 1) * 32;
    const long base = (long)(rowBase + r) * K + kk + cb;
    char* hB = smHi + r * AROW_B + cb * 2;
    char* lB = smLo + r * AROW_B + cb * 2;
    #pragma unroll
    for (int i = 0; i < 4; i++) {
        *(uint4*)(hB + i * 16) = *(const uint4*)(hi + base + i * 8);
        *(uint4*)(lB + i * 16) = *(const uint4*)(lo + base + i * 8);
    }
}

// ---------------------------------------------------------------------------
// Generic split-bf16 GEMM via mma.sync: C[M,N] = A[M,K] * B[N,K]^T  (fp32-acc)
//   128x128 tile/CTA, K chunks of 64, 8 warps (warpM=wid&3 ->32 rows,
//   warpN=wid>>2 ->64 cols). 3 MMAs per product: ah*bh + ah*bl + al*bh.
//   MODE 0: plain C write; MODE 1: scores (scale+mask, +g*M*N);
//   MODE 2: PV scatter into oacc.
// ---------------------------------------------------------------------------
template<int MODE, bool AF32, bool BF32>
__global__ void __launch_bounds__(256, 1)
tc_gemm(const void* Aa_, const void* Ab_, long arows1, long aSlabA, long aSlabB,
        const void* Ba_, const void* Bb_, long brows1, long bSlabA, long bSlabB,
        float* __restrict__ C, int M, int N, int K)
{
    extern __shared__ char sm[];

    const int tid = threadIdx.x;
    const int wid = tid >> 5;
    const int lane = tid & 31;
    const int g4 = lane >> 2;      // 0..7
    const int t4 = lane & 3;       // 0..3
    const int warpM = wid & 3;     // 4 warps along M (32 rows each)
    const int warpN = wid >> 2;    // 2 warps along N (64 cols each)
    const int gz = blockIdx.z;
    const int mBase = blockIdx.y * 128;
    const int nBase = blockIdx.x * 128;

    const float *Aaf = nullptr, *Abf = nullptr, *Baf = nullptr, *Bbf = nullptr;
    const __nv_bfloat16 *Ahp = nullptr, *Alp = nullptr, *Bhp = nullptr, *Blp = nullptr;
    if (AF32) {
        Aaf = (const float*)Aa_ + (long)gz * aSlabA;
        Abf = (const float*)Ab_ + (long)gz * aSlabB;
    } else {
        Ahp = (const __nv_bfloat16*)Aa_ + (long)gz * aSlabA;
        Alp = (const __nv_bfloat16*)Ab_ + (long)gz * aSlabB;
    }
    if (BF32) {
        Baf = (const float*)Ba_ + (long)gz * bSlabA;
        Bbf = (const float*)Bb_ + (long)gz * bSlabB;
    } else {
        Bhp = (const __nv_bfloat16*)Ba_ + (long)gz * bSlabA;
        Blp = (const __nv_bfloat16*)Bb_ + (long)gz * bSlabB;
    }

    float acc[16][4];   // [mt*8+nt][reg]
    #pragma unroll
    for (int i = 0; i < 16; i++)
        #pragma unroll
        for (int j = 0; j < 4; j++) acc[i][j] = 0.f;

    const int NC = K >> 6;

    // prologue: chunk 0 -> stage 0
    {
        char* st = sm;
        if (AF32) load_f32_tile(Aaf, Abf, arows1, K, mBase, 0, st, st + TILE_B, tid);
        else      load_bf16_tile(Ahp, Alp, K, mBase, 0, st, st + TILE_B, tid);
        if (BF32) load_f32_tile(Baf, Bbf, brows1, K, nBase, 0, st + 2*TILE_B, st + 3*TILE_B, tid);
        else      load_bf16_tile(Bhp, Blp, K, nBase, 0, st + 2*TILE_B, st + 3*TILE_B, tid);
        __syncthreads();
    }

    for (int c = 0; c < NC; c++) {
        char* st = sm + (c & 1) * STAGE_B;
        const char* Ah = st;
        const char* Al = st + TILE_B;
        const char* Bh = st + 2 * TILE_B;
        const char* Bl = st + 3 * TILE_B;

        #pragma unroll
        for (int ks = 0; ks < 4; ks++) {
            const int kc = ks * 16;                 // k within chunk
            const int kb = (kc + t4 * 2) * 2;       // byte col offset of frag pair

            // --- A fragments: 2 m-tiles, hi + lo
            uint32_t ah[2][4], al[2][4];
            #pragma unroll
            for (int mt = 0; mt < 2; mt++) {
                const int r0 = warpM * 32 + mt * 16 + g4;
                ah[mt][0] = *(const uint32_t*)(Ah + r0 * AROW_B + kb);
                ah[mt][1] = *(const uint32_t*)(Ah + (r0 + 8) * AROW_B + kb);
                ah[mt][2] = *(const uint32_t*)(Ah + r0 * AROW_B + kb + 16);
                ah[mt][3] = *(const uint32_t*)(Ah + (r0 + 8) * AROW_B + kb + 16);
                al[mt][0] = *(const uint32_t*)(Al + r0 * AROW_B + kb);
                al[mt][1] = *(const uint32_t*)(Al + (r0 + 8) * AROW_B + kb);
                al[mt][2] = *(const uint32_t*)(Al + r0 * AROW_B + kb + 16);
                al[mt][3] = *(const uint32_t*)(Al + (r0 + 8) * AROW_B + kb + 16);
            }
            // --- B fragments: 8 n-tiles, hi + lo (rows of smem = N dim)
            uint32_t bh[8][2], bl[8][2];
            #pragma unroll
            for (int nt = 0; nt < 8; nt++) {
                const int nr = warpN * 64 + nt * 8 + g4;
                bh[nt][0] = *(const uint32_t*)(Bh + nr * AROW_B + kb);
                bh[nt][1] = *(const uint32_t*)(Bh + nr * AROW_B + kb + 16);
                bl[nt][0] = *(const uint32_t*)(Bl + nr * AROW_B + kb);
                bl[nt][1] = *(const uint32_t*)(Bl + nr * AROW_B + kb + 16);
            }
            // --- 3-term split MMAs
            #pragma unroll
            for (int mt = 0; mt < 2; mt++)
                #pragma unroll
                for (int nt = 0; nt < 8; nt++) {
                    mma16816(acc[mt * 8 + nt], ah[mt], bh[nt]);
                    mma16816(acc[mt * 8 + nt], ah[mt], bl[nt]);
                    mma16816(acc[mt * 8 + nt], al[mt], bh[nt]);
                }
        }

        if (c + 1 < NC) {
            __syncthreads();   // all warps done reading stage (c+1)&1's old data
            char* nt_ = sm + ((c + 1) & 1) * STAGE_B;
            const int kk = (c + 1) << 6;
            if (AF32) load_f32_tile(Aaf, Abf, arows1, K, mBase, kk, nt_, nt_ + TILE_B, tid);
            else      load_bf16_tile(Ahp, Alp, K, mBase, kk, nt_, nt_ + TILE_B, tid);
            if (BF32) load_f32_tile(Baf, Bbf, brows1, K, nBase, kk, nt_ + 2*TILE_B, nt_ + 3*TILE_B, tid);
            else      load_bf16_tile(Bhp, Blp, K, nBase, kk, nt_ + 2*TILE_B, nt_ + 3*TILE_B, tid);
            __syncthreads();
        }
    }

    // ---- epilogue from register accumulators
    #pragma unroll
    for (int mt = 0; mt < 2; mt++) {
        #pragma unroll
        for (int nt = 0; nt < 8; nt++) {
            const float* a4 = acc[mt * 8 + nt];
            const int m0 = mBase + warpM * 32 + mt * 16 + g4;
            const int n0 = nBase + warpN * 64 + nt * 8 + t4 * 2;

            if (MODE == 0) {
                *(float2*)&C[(long)m0 * N + n0]       = make_float2(a4[0], a4[1]);
                *(float2*)&C[(long)(m0 + 8) * N + n0] = make_float2(a4[2], a4[3]);
            } else if (MODE == 1) {
                float* Cg = C + (long)gz * M * N;
                {
                    const int lim = 3968 + (m0 & 127);
                    float v0 = a4[0] * SCALE, v1 = a4[1] * SCALE;
                    if (n0     > lim) v0 = -1e30f;
                    if (n0 + 1 > lim) v1 = -1e30f;
                    *(float2*)&Cg[(long)m0 * N + n0] = make_float2(v0, v1);
                }
                {
                    const int m1 = m0 + 8;
                    const int lim = 3968 + (m1 & 127);
                    float v2 = a4[2] * SCALE, v3 = a4[3] * SCALE;
                    if (n0     > lim) v2 = -1e30f;
                    if (n0 + 1 > lim) v3 = -1e30f;
                    *(float2*)&Cg[(long)m1 * N + n0] = make_float2(v2, v3);
                }
            } else {
                // oacc[l*4096 + (gz*4 + r)*128 + n], m = r*128 + l
                {
                    const int l = m0 & 127, r = m0 >> 7;
                    *(float2*)&C[(long)l * 4096 + (gz * 4 + r) * 128 + n0] =
                        make_float2(a4[0], a4[1]);
                }
                {
                    const int m1 = m0 + 8;
                    const int l = m1 & 127, r = m1 >> 7;
                    *(float2*)&C[(long)l * 4096 + (gz * 4 + r) * 128 + n0] =
                        make_float2(a4[2], a4[3]);
                }
            }
        }
    }
}

// ---------------------------------------------------------------------------
// Row softmax over 4096 cols, writes P as bf16 hi/lo split
// ---------------------------------------------------------------------------
__global__ void __launch_bounds__(256) softmax_k(const float* __restrict__ scores,
                                                 __nv_bfloat16* __restrict__ ph,
                                                 __nv_bfloat16* __restrict__ pl)
{
    __shared__ float red[256];
    const long base = (long)blockIdx.x * 4096;
    const float* p = scores + base;
    const int tid = threadIdx.x;

    float v[16];
    float mx = -1e30f;
    #pragma unroll
    for (int i = 0; i < 16; i++) { v[i] = p[tid + i * 256]; mx = fmaxf(mx, v[i]); }
    red[tid] = mx; __syncthreads();
    #pragma unroll
    for (int s = 128; s > 0; s >>= 1) {
        if (tid < s) red[tid] = fmaxf(red[tid], red[tid + s]);
        __syncthreads();
    }
    mx = red[0]; __syncthreads();

    float sum = 0.f;
    #pragma unroll
    for (int i = 0; i < 16; i++) { v[i] = expf(v[i] - mx); sum += v[i]; }
    red[tid] = sum; __syncthreads();
    #pragma unroll
    for (int s = 128; s > 0; s >>= 1) {
        if (tid < s) red[tid] += red[tid + s];
        __syncthreads();
    }
    const float inv = 1.f / red[0];
    #pragma unroll
    for (int i = 0; i < 16; i++) {
        const float f = v[i] * inv;
        const __nv_bfloat16 h = __float2bfloat16(f);
        const __nv_bfloat16 l = __float2bfloat16(f - __bfloat162float(h));
        ph[base + tid + i * 256] = h;
        pl[base + tid + i * 256] = l;
    }
}

// ---------------------------------------------------------------------------
// V transpose + split: [g][s][d] (cacheV | v_new) -> [g][d][s] bf16 hi/lo
// ---------------------------------------------------------------------------
__global__ void vt_cvt(const float* __restrict__ cacheV, const float* __restrict__ vnew,
                       __nv_bfloat16* __restrict__ vh, __nv_bfloat16* __restrict__ vl)
{
    __shared__ float t[32][33];
    const int gidx = blockIdx.z;
    const int s0 = blockIdx.x * 32, d0 = blockIdx.y * 32;
    const int tx = threadIdx.x, ty = threadIdx.y;
    const int s = s0 + ty, d = d0 + tx;
    const float v = (s < STATE)
        ? cacheV[((long)gidx * STATE + s) * DD + d]
        : vnew [((long)gidx * TT + (s - STATE)) * DD + d];
    t[ty][tx] = v;
    __syncthreads();
    const float w = t[tx][ty];
    const __nv_bfloat16 h = __float2bfloat16(w);
    const __nv_bfloat16 l = __float2bfloat16(w - __bfloat162float(h));
    const long idx = ((long)gidx * DD + d0 + ty) * SS + s0 + tx;
    vh[idx] = h;
    vl[idx] = l;
}

// ---------------------------------------------------------------------------
// ane-norm + RoPE + transpose (validated in round 1)
// ---------------------------------------------------------------------------
__device__ __forceinline__ float block_sum_128(float v, float* red, int d)
{
    red[d] = v; __syncthreads();
    #pragma unroll
    for (int s = 64; s > 0; s >>= 1) {
        if (d < s) red[d] += red[d + s];
        __syncthreads();
    }
    float r = red[0]; __syncthreads();
    return r;
}

__global__ void __launch_bounds__(128)
norm_rope_k(const float* __restrict__ qproj, const float* __restrict__ kproj,
            const float* __restrict__ vproj,
            const float* __restrict__ cos_q, const float* __restrict__ sin_q,
            const float* __restrict__ cos_k, const float* __restrict__ sin_k,
            const float* __restrict__ qw, const float* __restrict__ kw,
            float* __restrict__ qh, float* __restrict__ out_k, float* __restrict__ out_v)
{
    __shared__ float red[128];
    __shared__ float y[128];
    const int b = blockIdx.x;
    const int d = threadIdx.x;

    if (b < LQ * HQ) {
        const int l = b / HQ, h = b % HQ;
        const float x = qproj[(long)l * 4096 + h * 128 + d];
        const float mean = block_sum_128(x, red, d) * (1.f / 128.f);
        const float xc = x - mean;
        const float var = block_sum_128(xc * xc, red, d) * (1.f / 128.f);
        const float yn = xc * rsqrtf(var + EPS) * qw[d];
        y[d] = yn; __syncthreads();
        const float rot = (d < HALF) ? -y[d + HALF] : y[d - HALF];
        const float o = yn * cos_q[l * 128 + d] + rot * sin_q[l * 128 + d];
        qh[((long)h * LQ + l) * 128 + d] = o;
    } else if (b < LQ * HQ + TT * HKV) {
        const int idx = b - LQ * HQ;
        const int t = idx / HKV, g = idx % HKV;
        const float x = kproj[(long)t * 1024 + g * 128 + d];
        const float mean = block_sum_128(x, red, d) * (1.f / 128.f);
        const float xc = x - mean;
        const float var = block_sum_128(xc * xc, red, d) * (1.f / 128.f);
        const float yn = xc * rsqrtf(var + EPS) * kw[d];
        y[d] = yn; __syncthreads();
        const float rot = (d < HALF) ? -y[d + HALF] : y[d - HALF];
        const float o = yn * cos_k[t * 128 + d] + rot * sin_k[t * 128 + d];
        out_k[((long)g * TT + t) * 128 + d] = o;
    } else {
        const int idx = b - LQ * HQ - TT * HKV;
        const int t = idx / HKV, g = idx % HKV;
        out_v[((long)g * TT + t) * 128 + d] = vproj[(long)t * 1024 + g * 128 + d];
    }
}

// ---------------------------------------------------------------------------
// Launch
// ---------------------------------------------------------------------------
extern "C" void kernel_launch(void* const* d_in, const int* in_sizes, int n_in,
                              void* d_out, int out_size)
{
    const float* x      = (const float*)d_in[0];
    const float* x_ctx  = (const float*)d_in[1];
    const float* cos_q  = (const float*)d_in[2];
    const float* sin_q  = (const float*)d_in[3];
    const float* cos_k  = (const float*)d_in[4];
    const float* sin_k  = (const float*)d_in[5];
    const float* cacheK = (const float*)d_in[6];
    const float* cacheV = (const float*)d_in[7];
    const float* Wq     = (const float*)d_in[9];
    const float* Wk     = (const float*)d_in[10];
    const float* Wv     = (const float*)d_in[11];
    const float* Wo     = (const float*)d_in[12];
    const float* qw     = (const float*)d_in[13];
    const float* kw     = (const float*)d_in[14];

    float* out   = (float*)d_out;
    float* out_k = out + OUT_ELEMS;
    float* out_v = out_k + K_ELEMS;

    float *p_qproj, *p_kproj, *p_vproj, *p_qh, *p_scores, *p_oacc;
    __nv_bfloat16 *p_ph, *p_pl, *p_vth, *p_vtl;
    cudaGetSymbolAddress((void**)&p_qproj,  g_qproj);
    cudaGetSymbolAddress((void**)&p_kproj,  g_kproj);
    cudaGetSymbolAddress((void**)&p_vproj,  g_vproj);
    cudaGetSymbolAddress((void**)&p_qh,     g_qh);
    cudaGetSymbolAddress((void**)&p_scores, g_scores);
    cudaGetSymbolAddress((void**)&p_oacc,   g_oacc);
    cudaGetSymbolAddress((void**)&p_ph,     g_ph);
    cudaGetSymbolAddress((void**)&p_pl,     g_pl);
    cudaGetSymbolAddress((void**)&p_vth,    g_vth);
    cudaGetSymbolAddress((void**)&p_vtl,    g_vtl);

    cudaFuncSetAttribute(tc_gemm<0, true, true>,
                         cudaFuncAttributeMaxDynamicSharedMemorySize, SMEM_BYTES);
    cudaFuncSetAttribute(tc_gemm<1, true, true>,
                         cudaFuncAttributeMaxDynamicSharedMemorySize, SMEM_BYTES);
    cudaFuncSetAttribute(tc_gemm<2, false, false>,
                         cudaFuncAttributeMaxDynamicSharedMemorySize, SMEM_BYTES);

    const long BIG = 1L << 40;

    // 1) Q projection: (128 x 4096) = x @ Wq^T
    tc_gemm<0, true, true><<<dim3(32, 1, 1), 256, SMEM_BYTES>>>(
        x, x, BIG, 0, 0, Wq, Wq, BIG, 0, 0, p_qproj, 128, 4096, 4096);

    // 2) K projection: (1024 x 1024) = [x_ctx; x] @ Wk^T
    tc_gemm<0, true, true><<<dim3(8, 8, 1), 256, SMEM_BYTES>>>(
        x_ctx, x, CTX, 0, 0, Wk, Wk, BIG, 0, 0, p_kproj, 1024, 1024, 4096);

    // 3) V projection
    tc_gemm<0, true, true><<<dim3(8, 8, 1), 256, SMEM_BYTES>>>(
        x_ctx, x, CTX, 0, 0, Wv, Wv, BIG, 0, 0, p_vproj, 1024, 1024, 4096);

    // 4) norm + rope + transpose (writes k/v outputs, fp32)
    norm_rope_k<<<LQ * HQ + 2 * TT * HKV, 128>>>(
        p_qproj, p_kproj, p_vproj, cos_q, sin_q, cos_k, sin_k, qw, kw,
        p_qh, out_k, out_v);

    // 5) V transpose + bf16 split: [g][d][s]
    vt_cvt<<<dim3(SS / 32, DD / 32, HKV), dim3(32, 32)>>>(cacheV, out_v, p_vth, p_vtl);

    // 6) scores: per g, (512 x 4096) = Q_g @ [cacheK_g; k_new_g]^T, scaled+masked
    tc_gemm<1, true, true><<<dim3(32, 4, 8), 256, SMEM_BYTES>>>(
        p_qh, p_qh, BIG, 512L * 128, 512L * 128,
        cacheK, out_k, STATE, (long)STATE * 128, (long)TT * 128,
        p_scores, 512, 4096, 128);

    // 7) softmax, emits P hi/lo bf16
    softmax_k<<<HQ * LQ, 256>>>(p_scores, p_ph, p_pl);

    // 8) O = P @ V: per g, (512 x 128), scatter into oacc[l][(4g+r)*128+d]
    tc_gemm<2, false, false><<<dim3(1, 4, 8), 256, SMEM_BYTES>>>(
        p_ph, p_pl, BIG, 512L * 4096, 512L * 4096,
        p_vth, p_vtl, BIG, (long)DD * SS, (long)DD * SS,
        p_oacc, 512, 128, 4096);

    // 9) final projection: (128 x 4096) = oacc @ Wo^T
    tc_gemm<0, true, true><<<dim3(32, 1, 1), 256, SMEM_BYTES>>>(
        p_oacc, p_oacc, BIG, 0, 0, Wo, Wo, BIG, 0, 0, out, 128, 4096, 4096);
}

// round 13
// speedup vs baseline: 2.5567x; 2.5567x over previous
#include <cuda_runtime.h>
#include <cuda_bf16.h>
#include <cstdint>

// ---------------------------------------------------------------------------
// Problem constants
// ---------------------------------------------------------------------------
#define HID   4096
#define LQ    128
#define CTX   896
#define TT    1024
#define STATE 3072
#define SS    4096
#define HQ    32
#define HKV   8
#define DD    128
#define HALF  64
#define EPS   1e-6f
#define SCALE 0.08838834764831845f

#define OUT_ELEMS   (LQ * HID)
#define K_ELEMS     (HKV * TT * DD)

// ---------------------------------------------------------------------------
// Scratch (device globals)
// ---------------------------------------------------------------------------
__device__ float g_qproj[LQ * HQ * DD];
__device__ float g_kproj[TT * HKV * DD];
__device__ float g_vproj[TT * HKV * DD];
__device__ float g_qh[HQ * LQ * DD];
__device__ float g_scores[HQ * LQ * SS];          // 64 MB
__device__ float g_oacc[LQ * HQ * DD];
__device__ float g_part[4 * 1024 * 1024];         // split-K partials
__device__ __nv_bfloat16 g_ph[HQ * LQ * SS];
__device__ __nv_bfloat16 g_pl[HQ * LQ * SS];
__device__ __nv_bfloat16 g_vth[HKV * DD * SS];    // V^T hi [g][d][s]
__device__ __nv_bfloat16 g_vtl[HKV * DD * SS];    // V^T lo

// ---------------------------------------------------------------------------
// mma.sync m16n8k16 bf16
// ---------------------------------------------------------------------------
__device__ __forceinline__ void mma16816(float* d, const uint32_t* a, const uint32_t* b)
{
    asm volatile(
        "mma.sync.aligned.m16n8k16.row.col.f32.bf16.bf16.f32 "
        "{%0,%1,%2,%3}, {%4,%5,%6,%7}, {%8,%9}, {%0,%1,%2,%3};"
        : "+f"(d[0]), "+f"(d[1]), "+f"(d[2]), "+f"(d[3])
        : "r"(a[0]), "r"(a[1]), "r"(a[2]), "r"(a[3]), "r"(b[0]), "r"(b[1]));
}

// ---------------------------------------------------------------------------
// SMEM tile geometry (144-byte row pitch: conflict-free fragment LDS)
// ---------------------------------------------------------------------------
#define AROW_B 144
#define TILE_B (128 * AROW_B)          // 18432
#define STAGE_B (4 * TILE_B)           // Ah | Al | Bh | Bl
#define SMEM_BYTES (2 * STAGE_B)       // 147456

// ---------------------------------------------------------------------------
// Prefetch structs + ldg/sts halves
// ---------------------------------------------------------------------------
struct PrefF32 { float4 v[8]; };
struct PrefB16 { uint4 h[4]; uint4 l[4]; };

__device__ __forceinline__ void ldg_f32(const float* p, PrefF32& r)
{
    #pragma unroll
    for (int i = 0; i < 8; i++) r.v[i] = *(const float4*)(p + i * 4);
}

__device__ __forceinline__ void sts_f32(const PrefF32& pf, char* hB, char* lB)
{
    #pragma unroll
    for (int i = 0; i < 8; i++) {
        float4 v = pf.v[i];
        __nv_bfloat162 h01 = __floats2bfloat162_rn(v.x, v.y);
        __nv_bfloat162 h23 = __floats2bfloat162_rn(v.z, v.w);
        float2 f01 = __bfloat1622float2(h01);
        float2 f23 = __bfloat1622float2(h23);
        __nv_bfloat162 l01 = __floats2bfloat162_rn(v.x - f01.x, v.y - f01.y);
        __nv_bfloat162 l23 = __floats2bfloat162_rn(v.z - f23.x, v.w - f23.y);
        *(uint2*)(hB + i * 8) = make_uint2(*(const uint32_t*)&h01, *(const uint32_t*)&h23);
        *(uint2*)(lB + i * 8) = make_uint2(*(const uint32_t*)&l01, *(const uint32_t*)&l23);
    }
}

__device__ __forceinline__ void ldg_b16(const __nv_bfloat16* hp, const __nv_bfloat16* lp,
                                        PrefB16& r)
{
    #pragma unroll
    for (int i = 0; i < 4; i++) {
        r.h[i] = *(const uint4*)(hp + i * 8);
        r.l[i] = *(const uint4*)(lp + i * 8);
    }
}

__device__ __forceinline__ void sts_b16(const PrefB16& p, char* hB, char* lB)
{
    #pragma unroll
    for (int i = 0; i < 4; i++) {
        *(uint4*)(hB + i * 16) = p.h[i];
        *(uint4*)(lB + i * 16) = p.l[i];
    }
}

// ---------------------------------------------------------------------------
// Split-bf16 GEMM via mma.sync, with split-K + register-prefetch pipeline.
//   C[M,N] = A[M,K_chunk] * B[N,K_chunk]^T partials (fp32 accumulate).
//   MODE 0: partial write C + kz*M*N              (projections)
//   MODE 1: direct write (scale + causal mask), C + gz*M*N   (scores, splits=1)
//   MODE 2: partial write C + (gz*splits+kz)*M*N  (PV)
//   F32OP: operands fp32 (split in-kernel) vs bf16 hi/lo pair (Aa=hi, Ab=lo)
// ---------------------------------------------------------------------------
template<int MODE, bool F32OP>
__global__ void __launch_bounds__(256, 1)
tc_gemm(const void* Aa_, const void* Ab_, long arows1, long aSlabA, long aSlabB,
        const void* Ba_, const void* Bb_, long brows1, long bSlabA, long bSlabB,
        float* __restrict__ C, int M, int N, int K, int splits)
{
    extern __shared__ char sm[];

    const int tid = threadIdx.x;
    const int wid = tid >> 5;
    const int lane = tid & 31;
    const int g4 = lane >> 2;
    const int t4 = lane & 3;
    const int warpM = wid & 3;
    const int warpN = wid >> 2;

    int gz, kz;
    if (MODE == 0)      { gz = 0;                      kz = blockIdx.z; }
    else if (MODE == 1) { gz = blockIdx.z;             kz = 0; }
    else                { gz = blockIdx.z / splits;    kz = blockIdx.z % splits; }

    const int mBase = blockIdx.y * 128;
    const int nBase = blockIdx.x * 128;
    const int Kc = K / splits;
    const int k0 = kz * Kc;
    const int NC = Kc >> 6;

    // ---- per-thread load pointers (row fixed, kk varies)
    const int r = tid >> 1;
    const int cb = (tid & 1) * 32;
    const int rowOff = r * AROW_B + cb * 2;

    const float *af = nullptr, *bf = nullptr;
    const __nv_bfloat16 *ah_p = nullptr, *al_p = nullptr, *bh_p = nullptr, *bl_p = nullptr;
    if (F32OP) {
        const long arow = mBase + r;
        const float* Aa = (const float*)Aa_ + (long)gz * aSlabA;
        const float* Ab = (const float*)Ab_ + (long)gz * aSlabB;
        af = ((arow < arows1) ? (Aa + arow * K) : (Ab + (arow - arows1) * K)) + cb;
        const long brow = nBase + r;
        const float* Ba = (const float*)Ba_ + (long)gz * bSlabA;
        const float* Bb = (const float*)Bb_ + (long)gz * bSlabB;
        bf = ((brow < brows1) ? (Ba + brow * K) : (Bb + (brow - brows1) * K)) + cb;
    } else {
        ah_p = (const __nv_bfloat16*)Aa_ + (long)gz * aSlabA + (long)(mBase + r) * K + cb;
        al_p = (const __nv_bfloat16*)Ab_ + (long)gz * aSlabB + (long)(mBase + r) * K + cb;
        bh_p = (const __nv_bfloat16*)Ba_ + (long)gz * bSlabA + (long)(nBase + r) * K + cb;
        bl_p = (const __nv_bfloat16*)Bb_ + (long)gz * bSlabB + (long)(nBase + r) * K + cb;
    }

    float acc[16][4];
    #pragma unroll
    for (int i = 0; i < 16; i++)
        #pragma unroll
        for (int j = 0; j < 4; j++) acc[i][j] = 0.f;

    PrefF32 paf, pbf;
    PrefB16 pab, pbb;

    // ---- prologue: chunk 0 -> stage 0
    if (F32OP) { ldg_f32(af + k0, paf); ldg_f32(bf + k0, pbf); }
    else       { ldg_b16(ah_p + k0, al_p + k0, pab); ldg_b16(bh_p + k0, bl_p + k0, pbb); }
    {
        char* st = sm;
        if (F32OP) {
            sts_f32(paf, st + rowOff, st + TILE_B + rowOff);
            sts_f32(pbf, st + 2 * TILE_B + rowOff, st + 3 * TILE_B + rowOff);
        } else {
            sts_b16(pab, st + rowOff, st + TILE_B + rowOff);
            sts_b16(pbb, st + 2 * TILE_B + rowOff, st + 3 * TILE_B + rowOff);
        }
    }
    __syncthreads();

    for (int c = 0; c < NC; c++) {
        // prefetch chunk c+1 into registers (covered by MMA latency below)
        if (c + 1 < NC) {
            const int kk = k0 + ((c + 1) << 6);
            if (F32OP) { ldg_f32(af + kk, paf); ldg_f32(bf + kk, pbf); }
            else       { ldg_b16(ah_p + kk, al_p + kk, pab); ldg_b16(bh_p + kk, bl_p + kk, pbb); }
        }

        char* st = sm + (c & 1) * STAGE_B;
        const char* Ah = st;
        const char* Al = st + TILE_B;
        const char* Bh = st + 2 * TILE_B;
        const char* Bl = st + 3 * TILE_B;

        #pragma unroll
        for (int ks = 0; ks < 4; ks++) {
            const int kb = (ks * 16 + t4 * 2) * 2;

            uint32_t afr[2][4], alr[2][4];
            #pragma unroll
            for (int mt = 0; mt < 2; mt++) {
                const int r0 = warpM * 32 + mt * 16 + g4;
                afr[mt][0] = *(const uint32_t*)(Ah + r0 * AROW_B + kb);
                afr[mt][1] = *(const uint32_t*)(Ah + (r0 + 8) * AROW_B + kb);
                afr[mt][2] = *(const uint32_t*)(Ah + r0 * AROW_B + kb + 16);
                afr[mt][3] = *(const uint32_t*)(Ah + (r0 + 8) * AROW_B + kb + 16);
                alr[mt][0] = *(const uint32_t*)(Al + r0 * AROW_B + kb);
                alr[mt][1] = *(const uint32_t*)(Al + (r0 + 8) * AROW_B + kb);
                alr[mt][2] = *(const uint32_t*)(Al + r0 * AROW_B + kb + 16);
                alr[mt][3] = *(const uint32_t*)(Al + (r0 + 8) * AROW_B + kb + 16);
            }
            uint32_t bhr[8][2], blr[8][2];
            #pragma unroll
            for (int nt = 0; nt < 8; nt++) {
                const int nr = warpN * 64 + nt * 8 + g4;
                bhr[nt][0] = *(const uint32_t*)(Bh + nr * AROW_B + kb);
                bhr[nt][1] = *(const uint32_t*)(Bh + nr * AROW_B + kb + 16);
                blr[nt][0] = *(const uint32_t*)(Bl + nr * AROW_B + kb);
                blr[nt][1] = *(const uint32_t*)(Bl + nr * AROW_B + kb + 16);
            }
            #pragma unroll
            for (int mt = 0; mt < 2; mt++)
                #pragma unroll
                for (int nt = 0; nt < 8; nt++) {
                    mma16816(acc[mt * 8 + nt], afr[mt], bhr[nt]);
                    mma16816(acc[mt * 8 + nt], afr[mt], blr[nt]);
                    mma16816(acc[mt * 8 + nt], alr[mt], bhr[nt]);
                }
        }

        if (c + 1 < NC) {
            char* nt_ = sm + ((c + 1) & 1) * STAGE_B;
            if (F32OP) {
                sts_f32(paf, nt_ + rowOff, nt_ + TILE_B + rowOff);
                sts_f32(pbf, nt_ + 2 * TILE_B + rowOff, nt_ + 3 * TILE_B + rowOff);
            } else {
                sts_b16(pab, nt_ + rowOff, nt_ + TILE_B + rowOff);
                sts_b16(pbb, nt_ + 2 * TILE_B + rowOff, nt_ + 3 * TILE_B + rowOff);
            }
            __syncthreads();
        }
    }

    // ---- epilogue
    float* Cp;
    if (MODE == 0)      Cp = C + (long)kz * M * N;
    else if (MODE == 1) Cp = C + (long)gz * M * N;
    else                Cp = C + (long)(gz * splits + kz) * M * N;

    #pragma unroll
    for (int mt = 0; mt < 2; mt++) {
        #pragma unroll
        for (int nt = 0; nt < 8; nt++) {
            const float* a4 = acc[mt * 8 + nt];
            const int m0 = mBase + warpM * 32 + mt * 16 + g4;
            const int n0 = nBase + warpN * 64 + nt * 8 + t4 * 2;

            if (MODE == 1) {
                {
                    const int lim = 3968 + (m0 & 127);
                    float v0 = a4[0] * SCALE, v1 = a4[1] * SCALE;
                    if (n0     > lim) v0 = -1e30f;
                    if (n0 + 1 > lim) v1 = -1e30f;
                    *(float2*)&Cp[(long)m0 * N + n0] = make_float2(v0, v1);
                }
                {
                    const int m1 = m0 + 8;
                    const int lim = 3968 + (m1 & 127);
                    float v2 = a4[2] * SCALE, v3 = a4[3] * SCALE;
                    if (n0     > lim) v2 = -1e30f;
                    if (n0 + 1 > lim) v3 = -1e30f;
                    *(float2*)&Cp[(long)m1 * N + n0] = make_float2(v2, v3);
                }
            } else {
                *(float2*)&Cp[(long)m0 * N + n0]       = make_float2(a4[0], a4[1]);
                *(float2*)&Cp[(long)(m0 + 8) * N + n0] = make_float2(a4[2], a4[3]);
            }
        }
    }
}

// ---------------------------------------------------------------------------
// Split-K reductions (deterministic; validated in round 1)
// ---------------------------------------------------------------------------
__global__ void reduce_sum(const float* __restrict__ part, float* __restrict__ C,
                           int MN, int splits)
{
    const int i = blockIdx.x * 256 + threadIdx.x;
    if (i < MN) {
        float s = 0.f;
        for (int z = 0; z < splits; z++) s += part[(long)z * MN + i];
        C[i] = s;
    }
}

// PV partials: [(g*4+kz)][512][128] -> oacc[l*4096 + (g*4+r)*128 + n]
__global__ void reduce_o4(const float* __restrict__ part, float* __restrict__ o)
{
    const int i = blockIdx.x * 256 + threadIdx.x;   // 0..524287
    const int g = i >> 16;
    const int rem = i & 65535;
    const int m = rem >> 7;
    const int n = rem & 127;
    float s = 0.f;
    #pragma unroll
    for (int z = 0; z < 4; z++)
        s += part[(((long)(g * 4 + z)) << 16) + rem];
    const int h = g * 4 + (m >> 7);
    const int l = m & 127;
    o[(long)l * 4096 + h * 128 + n] = s;
}

// ---------------------------------------------------------------------------
// Row softmax over 4096 cols, writes P as bf16 hi/lo split
// ---------------------------------------------------------------------------
__global__ void __launch_bounds__(256) softmax_k(const float* __restrict__ scores,
                                                 __nv_bfloat16* __restrict__ ph,
                                                 __nv_bfloat16* __restrict__ pl)
{
    __shared__ float red[256];
    const long base = (long)blockIdx.x * 4096;
    const float* p = scores + base;
    const int tid = threadIdx.x;

    float v[16];
    float mx = -1e30f;
    #pragma unroll
    for (int i = 0; i < 16; i++) { v[i] = p[tid + i * 256]; mx = fmaxf(mx, v[i]); }
    red[tid] = mx; __syncthreads();
    #pragma unroll
    for (int s = 128; s > 0; s >>= 1) {
        if (tid < s) red[tid] = fmaxf(red[tid], red[tid + s]);
        __syncthreads();
    }
    mx = red[0]; __syncthreads();

    float sum = 0.f;
    #pragma unroll
    for (int i = 0; i < 16; i++) { v[i] = expf(v[i] - mx); sum += v[i]; }
    red[tid] = sum; __syncthreads();
    #pragma unroll
    for (int s = 128; s > 0; s >>= 1) {
        if (tid < s) red[tid] += red[tid + s];
        __syncthreads();
    }
    const float inv = 1.f / red[0];
    #pragma unroll
    for (int i = 0; i < 16; i++) {
        const float f = v[i] * inv;
        const __nv_bfloat16 h = __float2bfloat16(f);
        const __nv_bfloat16 l = __float2bfloat16(f - __bfloat162float(h));
        ph[base + tid + i * 256] = h;
        pl[base + tid + i * 256] = l;
    }
}

// ---------------------------------------------------------------------------
// V transpose + split: [g][s][d] -> [g][d][s] bf16 hi/lo
// ---------------------------------------------------------------------------
__global__ void vt_cvt(const float* __restrict__ cacheV, const float* __restrict__ vnew,
                       __nv_bfloat16* __restrict__ vh, __nv_bfloat16* __restrict__ vl)
{
    __shared__ float t[32][33];
    const int gidx = blockIdx.z;
    const int s0 = blockIdx.x * 32, d0 = blockIdx.y * 32;
    const int tx = threadIdx.x, ty = threadIdx.y;
    const int s = s0 + ty, d = d0 + tx;
    const float v = (s < STATE)
        ? cacheV[((long)gidx * STATE + s) * DD + d]
        : vnew [((long)gidx * TT + (s - STATE)) * DD + d];
    t[ty][tx] = v;
    __syncthreads();
    const float w = t[tx][ty];
    const __nv_bfloat16 h = __float2bfloat16(w);
    const __nv_bfloat16 l = __float2bfloat16(w - __bfloat162float(h));
    const long idx = ((long)gidx * DD + d0 + ty) * SS + s0 + tx;
    vh[idx] = h;
    vl[idx] = l;
}

// ---------------------------------------------------------------------------
// ane-norm + RoPE + transpose (validated in round 1)
// ---------------------------------------------------------------------------
__device__ __forceinline__ float block_sum_128(float v, float* red, int d)
{
    red[d] = v; __syncthreads();
    #pragma unroll
    for (int s = 64; s > 0; s >>= 1) {
        if (d < s) red[d] += red[d + s];
        __syncthreads();
    }
    float r = red[0]; __syncthreads();
    return r;
}

__global__ void __launch_bounds__(128)
norm_rope_k(const float* __restrict__ qproj, const float* __restrict__ kproj,
            const float* __restrict__ vproj,
            const float* __restrict__ cos_q, const float* __restrict__ sin_q,
            const float* __restrict__ cos_k, const float* __restrict__ sin_k,
            const float* __restrict__ qw, const float* __restrict__ kw,
            float* __restrict__ qh, float* __restrict__ out_k, float* __restrict__ out_v)
{
    __shared__ float red[128];
    __shared__ float y[128];
    const int b = blockIdx.x;
    const int d = threadIdx.x;

    if (b < LQ * HQ) {
        const int l = b / HQ, h = b % HQ;
        const float x = qproj[(long)l * 4096 + h * 128 + d];
        const float mean = block_sum_128(x, red, d) * (1.f / 128.f);
        const float xc = x - mean;
        const float var = block_sum_128(xc * xc, red, d) * (1.f / 128.f);
        const float yn = xc * rsqrtf(var + EPS) * qw[d];
        y[d] = yn; __syncthreads();
        const float rot = (d < HALF) ? -y[d + HALF] : y[d - HALF];
        const float o = yn * cos_q[l * 128 + d] + rot * sin_q[l * 128 + d];
        qh[((long)h * LQ + l) * 128 + d] = o;
    } else if (b < LQ * HQ + TT * HKV) {
        const int idx = b - LQ * HQ;
        const int t = idx / HKV, g = idx % HKV;
        const float x = kproj[(long)t * 1024 + g * 128 + d];
        const float mean = block_sum_128(x, red, d) * (1.f / 128.f);
        const float xc = x - mean;
        const float var = block_sum_128(xc * xc, red, d) * (1.f / 128.f);
        const float yn = xc * rsqrtf(var + EPS) * kw[d];
        y[d] = yn; __syncthreads();
        const float rot = (d < HALF) ? -y[d + HALF] : y[d - HALF];
        const float o = yn * cos_k[t * 128 + d] + rot * sin_k[t * 128 + d];
        out_k[((long)g * TT + t) * 128 + d] = o;
    } else {
        const int idx = b - LQ * HQ - TT * HKV;
        const int t = idx / HKV, g = idx % HKV;
        out_v[((long)g * TT + t) * 128 + d] = vproj[(long)t * 1024 + g * 128 + d];
    }
}

// ---------------------------------------------------------------------------
// Launch
// ---------------------------------------------------------------------------
extern "C" void kernel_launch(void* const* d_in, const int* in_sizes, int n_in,
                              void* d_out, int out_size)
{
    const float* x      = (const float*)d_in[0];
    const float* x_ctx  = (const float*)d_in[1];
    const float* cos_q  = (const float*)d_in[2];
    const float* sin_q  = (const float*)d_in[3];
    const float* cos_k  = (const float*)d_in[4];
    const float* sin_k  = (const float*)d_in[5];
    const float* cacheK = (const float*)d_in[6];
    const float* cacheV = (const float*)d_in[7];
    const float* Wq     = (const float*)d_in[9];
    const float* Wk     = (const float*)d_in[10];
    const float* Wv     = (const float*)d_in[11];
    const float* Wo     = (const float*)d_in[12];
    const float* qw     = (const float*)d_in[13];
    const float* kw     = (const float*)d_in[14];

    float* out   = (float*)d_out;
    float* out_k = out + OUT_ELEMS;
    float* out_v = out_k + K_ELEMS;

    float *p_qproj, *p_kproj, *p_vproj, *p_qh, *p_scores, *p_oacc, *p_part;
    __nv_bfloat16 *p_ph, *p_pl, *p_vth, *p_vtl;
    cudaGetSymbolAddress((void**)&p_qproj,  g_qproj);
    cudaGetSymbolAddress((void**)&p_kproj,  g_kproj);
    cudaGetSymbolAddress((void**)&p_vproj,  g_vproj);
    cudaGetSymbolAddress((void**)&p_qh,     g_qh);
    cudaGetSymbolAddress((void**)&p_scores, g_scores);
    cudaGetSymbolAddress((void**)&p_oacc,   g_oacc);
    cudaGetSymbolAddress((void**)&p_part,   g_part);
    cudaGetSymbolAddress((void**)&p_ph,     g_ph);
    cudaGetSymbolAddress((void**)&p_pl,     g_pl);
    cudaGetSymbolAddress((void**)&p_vth,    g_vth);
    cudaGetSymbolAddress((void**)&p_vtl,    g_vtl);

    cudaFuncSetAttribute(tc_gemm<0, true>,
                         cudaFuncAttributeMaxDynamicSharedMemorySize, SMEM_BYTES);
    cudaFuncSetAttribute(tc_gemm<1, true>,
                         cudaFuncAttributeMaxDynamicSharedMemorySize, SMEM_BYTES);
    cudaFuncSetAttribute(tc_gemm<2, false>,
                         cudaFuncAttributeMaxDynamicSharedMemorySize, SMEM_BYTES);

    const long BIG = 1L << 40;

    // 1) Q projection: (128 x 4096), split-K 4
    tc_gemm<0, true><<<dim3(32, 1, 4), 256, SMEM_BYTES>>>(
        x, x, BIG, 0, 0, Wq, Wq, BIG, 0, 0, p_part, 128, 4096, 4096, 4);
    reduce_sum<<<OUT_ELEMS / 256, 256>>>(p_part, p_qproj, OUT_ELEMS, 4);

    // 2) K projection: (1024 x 1024), split-K 2
    tc_gemm<0, true><<<dim3(8, 8, 2), 256, SMEM_BYTES>>>(
        x_ctx, x, CTX, 0, 0, Wk, Wk, BIG, 0, 0, p_part, 1024, 1024, 4096, 2);
    reduce_sum<<<K_ELEMS / 256, 256>>>(p_part, p_kproj, K_ELEMS, 2);

    // 3) V projection, split-K 2
    tc_gemm<0, true><<<dim3(8, 8, 2), 256, SMEM_BYTES>>>(
        x_ctx, x, CTX, 0, 0, Wv, Wv, BIG, 0, 0, p_part, 1024, 1024, 4096, 2);
    reduce_sum<<<K_ELEMS / 256, 256>>>(p_part, p_vproj, K_ELEMS, 2);

    // 4) norm + rope + transpose (writes k/v outputs)
    norm_rope_k<<<LQ * HQ + 2 * TT * HKV, 128>>>(
        p_qproj, p_kproj, p_vproj, cos_q, sin_q, cos_k, sin_k, qw, kw,
        p_qh, out_k, out_v);

    // 5) V transpose + bf16 split
    vt_cvt<<<dim3(SS / 32, DD / 32, HKV), dim3(32, 32)>>>(cacheV, out_v, p_vth, p_vtl);

    // 6) scores: per g, (512 x 4096), K=128, no split
    tc_gemm<1, true><<<dim3(32, 4, 8), 256, SMEM_BYTES>>>(
        p_qh, p_qh, BIG, 512L * 128, 512L * 128,
        cacheK, out_k, STATE, (long)STATE * 128, (long)TT * 128,
        p_scores, 512, 4096, 128, 1);

    // 7) softmax -> P hi/lo
    softmax_k<<<HQ * LQ, 256>>>(p_scores, p_ph, p_pl);

    // 8) PV: per g, (512 x 128), split-K 4 -> partials -> scatter reduce
    tc_gemm<2, false><<<dim3(1, 4, 32), 256, SMEM_BYTES>>>(
        p_ph, p_pl, BIG, 512L * 4096, 512L * 4096,
        p_vth, p_vtl, BIG, (long)DD * SS, (long)DD * SS,
        p_part, 512, 128, 4096, 4);
    reduce_o4<<<OUT_ELEMS / 256, 256>>>(p_part, p_oacc);

    // 9) O projection: (128 x 4096), split-K 4
    tc_gemm<0, true><<<dim3(32, 1, 4), 256, SMEM_BYTES>>>(
        p_oacc, p_oacc, BIG, 0, 0, Wo, Wo, BIG, 0, 0, p_part, 128, 4096, 4096, 4);
    reduce_sum<<<OUT_ELEMS / 256, 256>>>(p_part, out, OUT_ELEMS, 4);
}